// round 9
// baseline (speedup 1.0000x reference)
#include <cuda_runtime.h>
#include <cuda_bf16.h>
#include <cstdint>
#include <cstddef>

// Problem dims
#define BB   128
#define TT   512
#define EE   256
#define UU   512
#define ZZ   2048          // 4*U
#define NCU  64            // u-groups (8 units each)
#define UT   8             // units per CTA group
#define CPC  32            // z-cols per CTA (4 gates * 8 units)
#define NCTA 128           // persistent grid

typedef __nv_bfloat16 bf16;

// ---------------- scratch (device globals; no allocations) ----------------
__device__ __align__(16) bf16  g_emb16[32000 * EE];          // bf16 embedding (16.4 MB)
__device__ __align__(16) bf16  g_WxGt [ZZ * EE];             // gathered Wx, [gc][k] (1 MB)
__device__ __align__(16) bf16  g_WhGt [NCU * CPC * UU];      // gathered Wh, [cu][jp][k] (2 MB)
__device__ __align__(16) float g_bG   [ZZ];                  // gathered bias
__device__ __align__(16) float g_zx   [(size_t)BB * TT * ZZ];// x@Wx + b, [t][b][gathered 2048] (512 MB)
__device__ __align__(1024) bf16 g_hbuf[2 * BB * UU];         // h double buffer, PLAIN rows of 1024B
// dataflow flags: [mg(2)][cu(64)][warp(4)], each padded to 128B
__device__ __align__(16) unsigned g_flags[2 * 64 * 4 * 32];

// gather map: gc -> original column
__device__ __forceinline__ int orig_col(int gc) {
    int cu   = gc >> 5;
    int gate = (gc >> 3) & 3;
    int j    = gc & 7;
    return gate * UU + cu * UT + j;
}

__device__ __forceinline__ float tanh_apx(float x) {
    float y;
    asm("tanh.approx.f32 %0, %1;" : "=f"(y) : "f"(x));
    return y;
}
__device__ __forceinline__ float sigm_apx(float x) {
    return fmaf(tanh_apx(0.5f * x), 0.5f, 0.5f);
}

__device__ __forceinline__ void mma_bf16(float& d0, float& d1, float& d2, float& d3,
                                         uint32_t a0, uint32_t a1, uint32_t a2, uint32_t a3,
                                         uint32_t b0, uint32_t b1) {
    asm volatile(
        "mma.sync.aligned.m16n8k16.row.col.f32.bf16.bf16.f32 "
        "{%0,%1,%2,%3}, {%4,%5,%6,%7}, {%8,%9}, {%0,%1,%2,%3};"
        : "+f"(d0), "+f"(d1), "+f"(d2), "+f"(d3)
        : "r"(a0), "r"(a1), "r"(a2), "r"(a3), "r"(b0), "r"(b1));
}

__device__ __forceinline__ void ldsm_x4(uint32_t& r0, uint32_t& r1, uint32_t& r2, uint32_t& r3,
                                        uint32_t addr) {
    asm volatile("ldmatrix.sync.aligned.m8n8.x4.shared.b16 {%0,%1,%2,%3}, [%4];"
                 : "=r"(r0), "=r"(r1), "=r"(r2), "=r"(r3) : "r"(addr));
}

__device__ __forceinline__ uint32_t ldpair(const bf16* p) {
    return *(const uint32_t*)p;
}

__device__ __forceinline__ void cp_async16(uint32_t dst_smem, const void* src) {
    asm volatile("cp.async.cg.shared.global [%0], [%1], 16;" :: "r"(dst_smem), "l"(src));
}
__device__ __forceinline__ unsigned ld_flag(const unsigned* p) {
    unsigned v;
    asm volatile("ld.relaxed.gpu.u32 %0, [%1];" : "=r"(v) : "l"(p) : "memory");
    return v;
}

// ---------------- init kernels ----------------
__global__ void k_cvt_emb(const float* __restrict__ src) {
    int n4 = 32000 * EE / 4;
    for (int i = blockIdx.x * blockDim.x + threadIdx.x; i < n4; i += gridDim.x * blockDim.x) {
        float4 v = *(const float4*)(src + (size_t)i * 4);
        bf16* d = g_emb16 + (size_t)i * 4;
        d[0] = __float2bfloat16(v.x);
        d[1] = __float2bfloat16(v.y);
        d[2] = __float2bfloat16(v.z);
        d[3] = __float2bfloat16(v.w);
    }
}

__global__ void k_gather_wx(const float* __restrict__ Wx, const float* __restrict__ bvec) {
    int n = ZZ * EE;
    for (int i = blockIdx.x * blockDim.x + threadIdx.x; i < n; i += gridDim.x * blockDim.x) {
        int gc = i >> 8;          // / 256
        int k  = i & 255;
        g_WxGt[i] = __float2bfloat16(Wx[(size_t)k * ZZ + orig_col(gc)]);
    }
    int t = blockIdx.x * blockDim.x + threadIdx.x;
    if (t < ZZ) g_bG[t] = bvec[orig_col(t)];
}

__global__ void k_gather_wh(const float* __restrict__ Wh) {
    int n = NCU * CPC * UU;
    for (int i = blockIdx.x * blockDim.x + threadIdx.x; i < n; i += gridDim.x * blockDim.x) {
        int cu = i >> 14;             // / (32*512)
        int jp = (i >> 9) & 31;
        int k  = i & 511;
        int gate = jp >> 3;
        int j    = jp & 7;
        g_WhGt[i] = __float2bfloat16(Wh[(size_t)k * ZZ + gate * UU + cu * UT + j]);
    }
}

__global__ void k_zero_state() {
    int tid = blockIdx.x * blockDim.x + threadIdx.x;
    int n = BB * UU;
    for (int i = tid; i < n; i += gridDim.x * blockDim.x)
        g_hbuf[i] = __float2bfloat16(0.0f);     // zero buffer 0 (read by step 0)
    for (int i = tid; i < 2 * 64 * 4 * 32; i += gridDim.x * blockDim.x)
        g_flags[i] = 0u;
}

// ---------------- phase 1: z_x = emb[sentence] @ Wx + b (gathered cols) ----------------
__global__ __launch_bounds__(256) void k_phase1(const int* __restrict__ sentence) {
    extern __shared__ __align__(16) char dsm1[];
    bf16* Bs   = (bf16*)dsm1;                       // stride 264
    bf16* As   = (bf16*)(dsm1 + 33792);             // stride 72
    int*  toks = (int*) (dsm1 + 33792 + 18432);

    int tid  = threadIdx.x;
    int warp = tid >> 5;
    int lane = tid & 31;
    int tg   = lane & 3;
    int gid  = lane >> 2;

    int n0    = (blockIdx.x & 31) * 64;
    int tbase = (blockIdx.x >> 5) * 16;

    int wm = (warp >> 1) * 32;
    int wn = (warp & 1) * 32;

#pragma unroll
    for (int r = 0; r < 8; r++) {
        int i   = tid + 256 * r;
        int row = i >> 5;
        int seg = i & 31;
        *(uint4*)(Bs + row * 264 + seg * 8) =
            *(const uint4*)(g_WxGt + (size_t)(n0 + row) * EE + seg * 8);
    }

    float bi[4][2];
#pragma unroll
    for (int nt = 0; nt < 4; nt++) {
        int col = n0 + wn + nt * 8 + tg * 2;
        bi[nt][0] = g_bG[col];
        bi[nt][1] = g_bG[col + 1];
    }
    __syncthreads();

    for (int tt = 0; tt < 16; tt++) {
        int t = tbase + tt;
        if (tid < 128) toks[tid] = sentence[tid * TT + t];
        __syncthreads();

        float acc[2][4][4];
#pragma unroll
        for (int mt = 0; mt < 2; mt++)
#pragma unroll
            for (int nt = 0; nt < 4; nt++)
#pragma unroll
                for (int q = 0; q < 4; q++) acc[mt][nt][q] = 0.0f;

        for (int kc = 0; kc < EE; kc += 64) {
#pragma unroll
            for (int r = 0; r < 4; r++) {
                int i   = tid + 256 * r;
                int row = i >> 3;
                int seg = i & 7;
                *(uint4*)(As + row * 72 + seg * 8) =
                    *(const uint4*)(g_emb16 + (size_t)toks[row] * EE + kc + seg * 8);
            }
            __syncthreads();

#pragma unroll
            for (int k16 = 0; k16 < 4; k16++) {
                int kbA = k16 * 16;
                int kbB = kc + k16 * 16;
                uint32_t a[2][4];
#pragma unroll
                for (int mt = 0; mt < 2; mt++) {
                    const bf16* p = As + (wm + mt * 16 + gid) * 72 + kbA + tg * 2;
                    a[mt][0] = ldpair(p);
                    a[mt][1] = ldpair(p + 8 * 72);
                    a[mt][2] = ldpair(p + 8);
                    a[mt][3] = ldpair(p + 8 * 72 + 8);
                }
                uint32_t bfr[4][2];
#pragma unroll
                for (int nt = 0; nt < 4; nt++) {
                    const bf16* p = Bs + (wn + nt * 8 + gid) * 264 + kbB + tg * 2;
                    bfr[nt][0] = ldpair(p);
                    bfr[nt][1] = ldpair(p + 8);
                }
#pragma unroll
                for (int mt = 0; mt < 2; mt++)
#pragma unroll
                    for (int nt = 0; nt < 4; nt++)
                        mma_bf16(acc[mt][nt][0], acc[mt][nt][1], acc[mt][nt][2], acc[mt][nt][3],
                                 a[mt][0], a[mt][1], a[mt][2], a[mt][3],
                                 bfr[nt][0], bfr[nt][1]);
            }
            __syncthreads();
        }

#pragma unroll
        for (int mt = 0; mt < 2; mt++) {
#pragma unroll
            for (int nt = 0; nt < 4; nt++) {
                int b   = wm + mt * 16 + gid;
                int col = n0 + wn + nt * 8 + tg * 2;
                size_t r0 = ((size_t)t * BB + b) * ZZ + col;
                size_t r2 = ((size_t)t * BB + b + 8) * ZZ + col;
                float2 v0 = { acc[mt][nt][0] + bi[nt][0], acc[mt][nt][1] + bi[nt][1] };
                float2 v2 = { acc[mt][nt][2] + bi[nt][0], acc[mt][nt][3] + bi[nt][1] };
                *(float2*)(g_zx + r0) = v0;
                *(float2*)(g_zx + r2) = v2;
            }
        }
    }
}

// ---------------- phase 2: persistent recurrence, dataflow (no CTA/grid barrier) ----------------
// 128 CTAs x 128 threads. cu = bx&63, mg = bx>>6. Warp w owns rows [m0+16w, +16).
// GEMM split into 32 k-chunks of 16 units; chunk j produced by CTAs (2j, 2j+1) warp w.
// Per-(cu,warp) epoch flags; depth-4 cp.async chunk pipeline, staggered start at own chunk.
// dyn smem: slabs 4 warps x 4 x 512B (8192) | Bs (Wh) 32x520 bf16 (33280)  -> 41472
__global__ __launch_bounds__(128) void k_recur() {
    extern __shared__ __align__(128) char dsm[];
    bf16* Bs = (bf16*)(dsm + 8192);

    uint32_t slabs_u32 = (uint32_t)__cvta_generic_to_shared(dsm);
    uint32_t Bs_u32    = slabs_u32 + 8192;

    int tid  = threadIdx.x;
    int warp = tid >> 5;
    int lane = tid & 31;
    int tg   = lane & 3;
    int gid  = lane >> 2;

    int cu = blockIdx.x & 63;
    int mg = blockIdx.x >> 6;
    int m0 = mg * 64;
    int wm = warp * 16;

    // preload Wh slice (32 x 512 bf16), stride 520 (conflict-free for B ldsm)
    {
        const bf16* Wp = g_WhGt + (size_t)cu * CPC * UU;
        for (int i = tid; i < 2048; i += 128) {
            int n   = i >> 6;
            int seg = i & 63;
            *(uint4*)(Bs + n * 520 + seg * 8) = *(const uint4*)(Wp + n * UU + seg * 8);
        }
    }
    __syncthreads();

    // per-lane constant addressing
    uint32_t warpSlab = slabs_u32 + (uint32_t)(warp * 2048);
    // LDGSTS dst offset inside a 512B slab (swizzled: 16 rows x 32B, XOR bit4 with row bit2)
    uint32_t dstoff = (uint32_t)((((lane >> 1) * 32 + (lane & 1) * 16) ^ (((lane >> 1) & 4) << 2)));
    // ldsm A offset in slab (same swizzle)
    {
    }
    uint32_t rA   = (uint32_t)(lane & 15);
    uint32_t aoff = (uint32_t)(((rA * 32 + ((lane & 16) ? 16u : 0u)) ^ ((rA & 4) << 2)));
    // B ldsm lane addresses (gate-aligned tiles; proven in R7/R8)
    uint32_t bAddr0 = Bs_u32 + (uint32_t)(((0  + (lane & 7) + ((lane & 16) ? 8 : 0)) * 520) * 2 + ((lane & 8) ? 16 : 0));
    uint32_t bAddr1 = Bs_u32 + (uint32_t)(((16 + (lane & 7) + ((lane & 16) ? 8 : 0)) * 520) * 2 + ((lane & 8) ? 16 : 0));

    // gate ownership: rows (m0+wm+gid, +8), units (cu*8 + tg*2, +1)
    int rowA = m0 + wm + gid;
    float c00 = 0.0f, c01 = 0.0f, c10 = 0.0f, c11 = 0.0f;

    // flags
    unsigned* myflag = g_flags + (size_t)(((mg * 64 + cu) * 4 + warp) * 32);
    const unsigned* snap0 = g_flags + (size_t)(((mg * 64 + 2 * lane)     * 4 + warp) * 32);
    const unsigned* snap1 = g_flags + (size_t)(((mg * 64 + 2 * lane + 1) * 4 + warp) * 32);

    // LDGSTS src: row = m0+wm+(lane>>1), byte col = chunk*32 + (lane&1)*16
    size_t srcrow = (size_t)(m0 + wm + (lane >> 1)) * 1024 + (size_t)((lane & 1) * 16);
    const char* hb = (const char*)g_hbuf;

    int c0 = cu >> 1;   // staggered chunk start (own units first)

    for (int t = 0; t < TT; t++) {
        const char* hsrc = hb + (size_t)(t & 1) * 131072;
        bf16*       hdst = g_hbuf + (size_t)((t + 1) & 1) * (BB * UU);

        // z_x prefetch (DRAM; long slack)
        const float* zxr0 = g_zx + ((size_t)t * BB + rowA) * ZZ + cu * CPC + tg * 2;
        const float* zxr1 = zxr0 + 8 * ZZ;
        float2 zi0 = *(const float2*)(zxr0);
        float2 zf0 = *(const float2*)(zxr0 + 8);
        float2 zg0 = *(const float2*)(zxr0 + 16);
        float2 zo0 = *(const float2*)(zxr0 + 24);
        float2 zi1 = *(const float2*)(zxr1);
        float2 zf1 = *(const float2*)(zxr1 + 8);
        float2 zg1 = *(const float2*)(zxr1 + 16);
        float2 zo1 = *(const float2*)(zxr1 + 24);

        // snapshot all 64 producer flags (lane-parallel) + readiness ballot
        unsigned f0 = ld_flag(snap0);
        unsigned f1 = ld_flag(snap1);
        unsigned rdy = __ballot_sync(0xffffffffu,
                                     (f0 >= (unsigned)t) && (f1 >= (unsigned)t));

        // ---- stage chunk helper (macro): pipeline index ji, chunk cj ----
#define CHK_STAGE(ji)                                                                   \
        {                                                                               \
            int cj_ = (c0 + (ji)) & 31;                                                 \
            if (!((rdy >> cj_) & 1u)) {                                                 \
                const unsigned* p0_ = g_flags + (size_t)(((mg * 64 + 2 * cj_)     * 4 + warp) * 32); \
                const unsigned* p1_ = g_flags + (size_t)(((mg * 64 + 2 * cj_ + 1) * 4 + warp) * 32); \
                unsigned v0_, v1_;                                                      \
                do { v0_ = ld_flag(p0_); v1_ = ld_flag(p1_); }                          \
                while (v0_ < (unsigned)t || v1_ < (unsigned)t);                         \
            }                                                                           \
            cp_async16(warpSlab + (uint32_t)(((ji) & 3) * 512) + dstoff,                \
                       hsrc + srcrow + (size_t)(cj_ * 32));                             \
            asm volatile("cp.async.commit_group;" ::: "memory");                        \
        }

        // prologue: fill pipeline with 4 chunks
        CHK_STAGE(0)
        CHK_STAGE(1)
        CHK_STAGE(2)
        CHK_STAGE(3)

        float acc[4][4];   // [gate][q]
#pragma unroll
        for (int g = 0; g < 4; g++)
#pragma unroll
            for (int q = 0; q < 4; q++) acc[g][q] = 0.0f;

#pragma unroll 4
        for (int i = 0; i < 32; i++) {
            asm volatile("cp.async.wait_group 3;" ::: "memory");
            int cj = (c0 + i) & 31;
            uint32_t aaddr = warpSlab + (uint32_t)((i & 3) * 512) + aoff;
            uint32_t kb = (uint32_t)(cj * 32);
            uint32_t a0, a1, a2, a3, b0, b1, b2, b3, b4, b5, b6, b7;
            ldsm_x4(a0, a1, a2, a3, aaddr);
            ldsm_x4(b0, b1, b2, b3, bAddr0 + kb);
            ldsm_x4(b4, b5, b6, b7, bAddr1 + kb);
            mma_bf16(acc[0][0], acc[0][1], acc[0][2], acc[0][3], a0, a1, a2, a3, b0, b1);
            mma_bf16(acc[1][0], acc[1][1], acc[1][2], acc[1][3], a0, a1, a2, a3, b2, b3);
            mma_bf16(acc[2][0], acc[2][1], acc[2][2], acc[2][3], a0, a1, a2, a3, b4, b5);
            mma_bf16(acc[3][0], acc[3][1], acc[3][2], acc[3][3], a0, a1, a2, a3, b6, b7);
            if (i + 4 < 32) {
                CHK_STAGE(i + 4)
            } else {
                asm volatile("cp.async.commit_group;" ::: "memory");  // keep 4 groups pending
            }
        }
#undef CHK_STAGE

        // gate update fully in registers
        {
            float i0 = sigm_apx(zi0.x + acc[0][0]), fg0 = sigm_apx(zf0.x + acc[1][0]);
            float gg0 = tanh_apx(zg0.x + acc[2][0]), o0 = sigm_apx(zo0.x + acc[3][0]);
            c00 = fg0 * c00 + i0 * gg0;
            float h00 = o0 * tanh_apx(c00);

            float i1 = sigm_apx(zi0.y + acc[0][1]), fg1 = sigm_apx(zf0.y + acc[1][1]);
            float gg1 = tanh_apx(zg0.y + acc[2][1]), o1 = sigm_apx(zo0.y + acc[3][1]);
            c01 = fg1 * c01 + i1 * gg1;
            float h01 = o1 * tanh_apx(c01);

            float i2 = sigm_apx(zi1.x + acc[0][2]), fg2 = sigm_apx(zf1.x + acc[1][2]);
            float gg2 = tanh_apx(zg1.x + acc[2][2]), o2 = sigm_apx(zo1.x + acc[3][2]);
            c10 = fg2 * c10 + i2 * gg2;
            float h10 = o2 * tanh_apx(c10);

            float i3 = sigm_apx(zi1.y + acc[0][3]), fg3 = sigm_apx(zf1.y + acc[1][3]);
            float gg3 = tanh_apx(zg1.y + acc[2][3]), o3 = sigm_apx(zo1.y + acc[3][3]);
            c11 = fg3 * c11 + i3 * gg3;
            float h11 = o3 * tanh_apx(c11);

            __nv_bfloat162 hA, hB;
            hA.x = __float2bfloat16(h00); hA.y = __float2bfloat16(h01);
            hB.x = __float2bfloat16(h10); hB.y = __float2bfloat16(h11);
            size_t base = (size_t)rowA * UU + cu * UT + tg * 2;
            *(__nv_bfloat162*)(hdst + base)          = hA;
            *(__nv_bfloat162*)(hdst + base + 8 * UU) = hB;
        }

        // publish: all lanes' stores drained, then bump this (cu,warp) epoch
        __syncwarp();
        if (lane == 0) {
            asm volatile("fence.acq_rel.gpu;" ::: "memory");
            asm volatile("st.relaxed.gpu.u32 [%0], %1;" :: "l"(myflag), "r"(t + 1) : "memory");
        }
    }
}

// ---------------- head: per-batch MLP (h(512) in buffer 0, plain layout) ----------------
__global__ __launch_bounds__(128) void k_head(const float* __restrict__ W1, const float* __restrict__ b1,
                                              const float* __restrict__ W2, const float* __restrict__ b2,
                                              const float* __restrict__ W3, const float* __restrict__ b3,
                                              float* __restrict__ out) {
    __shared__ float hsm[UU];
    __shared__ float h1[128];
    __shared__ float red[64];
    int b   = blockIdx.x;
    int tid = threadIdx.x;

    for (int i = tid; i < UU; i += 128)
        hsm[i] = __bfloat162float(g_hbuf[(size_t)b * UU + i]);
    __syncthreads();

    float a1 = b1[tid];
#pragma unroll 8
    for (int k = 0; k < UU; k++) a1 += hsm[k] * W1[k * 128 + tid];
    h1[tid] = fmaxf(a1, 0.0f);
    __syncthreads();

    if (tid < 64) {
        float a2 = b2[tid];
#pragma unroll 8
        for (int k = 0; k < 128; k++) a2 += h1[k] * W2[k * 64 + tid];
        a2 = fmaxf(a2, 0.0f);
        red[tid] = a2 * W3[tid];
    }
    __syncthreads();

    if (tid == 0) {
        float s = b3[0];
#pragma unroll 8
        for (int k = 0; k < 64; k++) s += red[k];
        out[b] = 1.0f / (1.0f + expf(-s));
    }
}

// ---------------- launch ----------------
extern "C" void kernel_launch(void* const* d_in, const int* in_sizes, int n_in,
                              void* d_out, int out_size) {
    const int*   sentence = (const int*)  d_in[0];
    const float* emb      = (const float*)d_in[1];
    const float* Wx       = (const float*)d_in[2];
    const float* Wh       = (const float*)d_in[3];
    const float* bvec     = (const float*)d_in[4];
    const float* W1       = (const float*)d_in[5];
    const float* b1       = (const float*)d_in[6];
    const float* W2       = (const float*)d_in[7];
    const float* b2       = (const float*)d_in[8];
    const float* W3       = (const float*)d_in[9];
    const float* b3       = (const float*)d_in[10];
    float* out = (float*)d_out;

    static bool attr_done = false;
    if (!attr_done) {
        cudaFuncSetAttribute(k_phase1, cudaFuncAttributeMaxDynamicSharedMemorySize, 52736);
        cudaFuncSetAttribute(k_recur,  cudaFuncAttributeMaxDynamicSharedMemorySize, 41472);
        attr_done = true;
    }

    k_cvt_emb<<<4096, 256>>>(emb);
    k_gather_wx<<<2048, 256>>>(Wx, bvec);
    k_gather_wh<<<4096, 256>>>(Wh);
    k_zero_state<<<256, 256>>>();

    k_phase1<<<1024, 256, 52736>>>(sentence);

    k_recur<<<NCTA, 128, 41472>>>();

    k_head<<<128, 128>>>(W1, b1, W2, b2, W3, b3, out);
}

// round 10
// speedup vs baseline: 1.4673x; 1.4673x over previous
#include <cuda_runtime.h>
#include <cuda_bf16.h>
#include <cstdint>
#include <cstddef>

// Problem dims
#define BB   128
#define TT   512
#define EE   256
#define UU   512
#define ZZ   2048          // 4*U
#define NCU  64            // u-groups (8 units each)
#define UT   8             // units per CTA group
#define CPC  32            // z-cols per u-group (4 gates * 8 units)
#define CSZ  16            // cluster size

typedef __nv_bfloat16 bf16;

// ---------------- scratch (device globals; no allocations) ----------------
__device__ __align__(16) bf16  g_emb16[32000 * EE];          // bf16 embedding (16.4 MB)
__device__ __align__(16) bf16  g_WxGt [ZZ * EE];             // gathered Wx, [gc][k] (1 MB)
__device__ __align__(16) bf16  g_WhGt [NCU * CPC * UU];      // gathered Wh, [cu][jp][k] (2 MB)
__device__ __align__(16) float g_bG   [ZZ];                  // gathered bias
__device__ __align__(16) float g_zx   [(size_t)BB * TT * ZZ];// x@Wx + b, [t][b][gathered 2048] (512 MB)
__device__ __align__(1024) bf16 g_hbuf[BB * UU];             // final h for the head

// gather map: gc -> original column
__device__ __forceinline__ int orig_col(int gc) {
    int cu   = gc >> 5;
    int gate = (gc >> 3) & 3;
    int j    = gc & 7;
    return gate * UU + cu * UT + j;
}

__device__ __forceinline__ float tanh_apx(float x) {
    float y;
    asm("tanh.approx.f32 %0, %1;" : "=f"(y) : "f"(x));
    return y;
}
__device__ __forceinline__ float sigm_apx(float x) {
    return fmaf(tanh_apx(0.5f * x), 0.5f, 0.5f);
}

__device__ __forceinline__ void mma_bf16(float& d0, float& d1, float& d2, float& d3,
                                         uint32_t a0, uint32_t a1, uint32_t a2, uint32_t a3,
                                         uint32_t b0, uint32_t b1) {
    asm volatile(
        "mma.sync.aligned.m16n8k16.row.col.f32.bf16.bf16.f32 "
        "{%0,%1,%2,%3}, {%4,%5,%6,%7}, {%8,%9}, {%0,%1,%2,%3};"
        : "+f"(d0), "+f"(d1), "+f"(d2), "+f"(d3)
        : "r"(a0), "r"(a1), "r"(a2), "r"(a3), "r"(b0), "r"(b1));
}

__device__ __forceinline__ void ldsm_x4(uint32_t& r0, uint32_t& r1, uint32_t& r2, uint32_t& r3,
                                        uint32_t addr) {
    asm volatile("ldmatrix.sync.aligned.m8n8.x4.shared.b16 {%0,%1,%2,%3}, [%4];"
                 : "=r"(r0), "=r"(r1), "=r"(r2), "=r"(r3) : "r"(addr));
}

__device__ __forceinline__ uint32_t ldpair(const bf16* p) {
    return *(const uint32_t*)p;
}

__device__ __forceinline__ uint32_t cluster_rank() {
    uint32_t r;
    asm("mov.u32 %0, %%cluster_ctarank;" : "=r"(r));
    return r;
}
__device__ __forceinline__ uint32_t mapa_u32(uint32_t local, uint32_t rank) {
    uint32_t r;
    asm("mapa.shared::cluster.u32 %0, %1, %2;" : "=r"(r) : "r"(local), "r"(rank));
    return r;
}
__device__ __forceinline__ void st_cluster_u32(uint32_t addr, uint32_t v) {
    asm volatile("st.shared::cluster.u32 [%0], %1;" :: "r"(addr), "r"(v) : "memory");
}
__device__ __forceinline__ void cluster_arrive() {
    asm volatile("barrier.cluster.arrive.aligned;" ::: "memory");
}
__device__ __forceinline__ void cluster_wait() {
    asm volatile("barrier.cluster.wait.aligned;" ::: "memory");
}

// ---------------- init kernels ----------------
__global__ void k_cvt_emb(const float* __restrict__ src) {
    int n4 = 32000 * EE / 4;
    for (int i = blockIdx.x * blockDim.x + threadIdx.x; i < n4; i += gridDim.x * blockDim.x) {
        float4 v = *(const float4*)(src + (size_t)i * 4);
        bf16* d = g_emb16 + (size_t)i * 4;
        d[0] = __float2bfloat16(v.x);
        d[1] = __float2bfloat16(v.y);
        d[2] = __float2bfloat16(v.z);
        d[3] = __float2bfloat16(v.w);
    }
}

__global__ void k_gather_wx(const float* __restrict__ Wx, const float* __restrict__ bvec) {
    int n = ZZ * EE;
    for (int i = blockIdx.x * blockDim.x + threadIdx.x; i < n; i += gridDim.x * blockDim.x) {
        int gc = i >> 8;          // / 256
        int k  = i & 255;
        g_WxGt[i] = __float2bfloat16(Wx[(size_t)k * ZZ + orig_col(gc)]);
    }
    int t = blockIdx.x * blockDim.x + threadIdx.x;
    if (t < ZZ) g_bG[t] = bvec[orig_col(t)];
}

__global__ void k_gather_wh(const float* __restrict__ Wh) {
    int n = NCU * CPC * UU;
    for (int i = blockIdx.x * blockDim.x + threadIdx.x; i < n; i += gridDim.x * blockDim.x) {
        int cu = i >> 14;             // / (32*512)
        int jp = (i >> 9) & 31;
        int k  = i & 511;
        int gate = jp >> 3;
        int j    = jp & 7;
        g_WhGt[i] = __float2bfloat16(Wh[(size_t)k * ZZ + gate * UU + cu * UT + j]);
    }
}

// ---------------- phase 1: z_x = emb[sentence] @ Wx + b (gathered cols) ----------------
__global__ __launch_bounds__(256) void k_phase1(const int* __restrict__ sentence) {
    extern __shared__ __align__(16) char dsm1[];
    bf16* Bs   = (bf16*)dsm1;                       // stride 264
    bf16* As   = (bf16*)(dsm1 + 33792);             // stride 72
    int*  toks = (int*) (dsm1 + 33792 + 18432);

    int tid  = threadIdx.x;
    int warp = tid >> 5;
    int lane = tid & 31;
    int tg   = lane & 3;
    int gid  = lane >> 2;

    int n0    = (blockIdx.x & 31) * 64;
    int tbase = (blockIdx.x >> 5) * 16;

    int wm = (warp >> 1) * 32;
    int wn = (warp & 1) * 32;

#pragma unroll
    for (int r = 0; r < 8; r++) {
        int i   = tid + 256 * r;
        int row = i >> 5;
        int seg = i & 31;
        *(uint4*)(Bs + row * 264 + seg * 8) =
            *(const uint4*)(g_WxGt + (size_t)(n0 + row) * EE + seg * 8);
    }

    float bi[4][2];
#pragma unroll
    for (int nt = 0; nt < 4; nt++) {
        int col = n0 + wn + nt * 8 + tg * 2;
        bi[nt][0] = g_bG[col];
        bi[nt][1] = g_bG[col + 1];
    }
    __syncthreads();

    for (int tt = 0; tt < 16; tt++) {
        int t = tbase + tt;
        if (tid < 128) toks[tid] = sentence[tid * TT + t];
        __syncthreads();

        float acc[2][4][4];
#pragma unroll
        for (int mt = 0; mt < 2; mt++)
#pragma unroll
            for (int nt = 0; nt < 4; nt++)
#pragma unroll
                for (int q = 0; q < 4; q++) acc[mt][nt][q] = 0.0f;

        for (int kc = 0; kc < EE; kc += 64) {
#pragma unroll
            for (int r = 0; r < 4; r++) {
                int i   = tid + 256 * r;
                int row = i >> 3;
                int seg = i & 7;
                *(uint4*)(As + row * 72 + seg * 8) =
                    *(const uint4*)(g_emb16 + (size_t)toks[row] * EE + kc + seg * 8);
            }
            __syncthreads();

#pragma unroll
            for (int k16 = 0; k16 < 4; k16++) {
                int kbA = k16 * 16;
                int kbB = kc + k16 * 16;
                uint32_t a[2][4];
#pragma unroll
                for (int mt = 0; mt < 2; mt++) {
                    const bf16* p = As + (wm + mt * 16 + gid) * 72 + kbA + tg * 2;
                    a[mt][0] = ldpair(p);
                    a[mt][1] = ldpair(p + 8 * 72);
                    a[mt][2] = ldpair(p + 8);
                    a[mt][3] = ldpair(p + 8 * 72 + 8);
                }
                uint32_t bfr[4][2];
#pragma unroll
                for (int nt = 0; nt < 4; nt++) {
                    const bf16* p = Bs + (wn + nt * 8 + gid) * 264 + kbB + tg * 2;
                    bfr[nt][0] = ldpair(p);
                    bfr[nt][1] = ldpair(p + 8);
                }
#pragma unroll
                for (int mt = 0; mt < 2; mt++)
#pragma unroll
                    for (int nt = 0; nt < 4; nt++)
                        mma_bf16(acc[mt][nt][0], acc[mt][nt][1], acc[mt][nt][2], acc[mt][nt][3],
                                 a[mt][0], a[mt][1], a[mt][2], a[mt][3],
                                 bfr[nt][0], bfr[nt][1]);
            }
            __syncthreads();
        }

#pragma unroll
        for (int mt = 0; mt < 2; mt++) {
#pragma unroll
            for (int nt = 0; nt < 4; nt++) {
                int b   = wm + mt * 16 + gid;
                int col = n0 + wn + nt * 8 + tg * 2;
                size_t r0 = ((size_t)t * BB + b) * ZZ + col;
                size_t r2 = ((size_t)t * BB + b + 8) * ZZ + col;
                float2 v0 = { acc[mt][nt][0] + bi[nt][0], acc[mt][nt][1] + bi[nt][1] };
                float2 v2 = { acc[mt][nt][2] + bi[nt][0], acc[mt][nt][3] + bi[nt][1] };
                *(float2*)(g_zx + r0) = v0;
                *(float2*)(g_zx + r2) = v2;
            }
        }
    }
}

// ---------------- phase 2: persistent recurrence, cluster-16 + DSMEM h-exchange ----------------
// 8 clusters x 16 CTAs x 128 threads. Cluster c owns batch rows [16c, 16c+16).
// CTA rank r holds resident Wh slice for gathered cols [128r, 128r+128) (u-groups 4r..4r+3).
// Warp w handles u-group 4r+w (32 gate cols), rows = the cluster's 16 batch rows.
// h exchanged via st.shared::cluster into per-CTA double-buffered smem; one cluster
// barrier per step. Cell state c in registers.
// dyn smem: Bs 128x520 bf16 (133120) | Hb 2 x 16x520 bf16 (33280)  -> 166400
__global__ __launch_bounds__(128) __cluster_dims__(CSZ, 1, 1) void k_recur() {
    extern __shared__ __align__(128) char dsm[];
    bf16* Bs = (bf16*)dsm;                           // Wh slice, stride 520
    bf16* Hb = (bf16*)(dsm + 133120);                // 2 h buffers, 16 rows x stride 520

    uint32_t base_u32 = (uint32_t)__cvta_generic_to_shared(dsm);
    uint32_t Bs_u32   = base_u32;
    uint32_t Hb_u32   = base_u32 + 133120;

    int tid  = threadIdx.x;
    int warp = tid >> 5;
    int lane = tid & 31;
    int tg   = lane & 3;
    int gid  = lane >> 2;

    uint32_t rank = cluster_rank();
    int clu = blockIdx.x >> 4;         // cluster id (8)
    int r0  = clu * CSZ;               // batch-row base of this cluster

    // load Wh block: 128 gathered cols x 512 K  (g_WhGt rows 128*rank .. +128)
    {
        const bf16* Wp = g_WhGt + (size_t)rank * 128 * UU;
        for (int i = tid; i < 8192; i += 128) {      // 8192 uint4
            int row = i >> 6;
            int seg = i & 63;
            *(uint4*)(Bs + row * 520 + seg * 8) = *(const uint4*)(Wp + row * UU + seg * 8);
        }
    }
    // zero both h buffers (33280 B = 2080 uint4)
    {
        uint4 z = make_uint4(0, 0, 0, 0);
        for (int i = tid; i < 2080; i += 128)
            *(uint4*)((char*)Hb + i * 16) = z;
    }
    __syncthreads();
    // initial cluster barrier: no remote write may land before everyone finished zeroing
    cluster_arrive();
    cluster_wait();

    // ldsm A lane address (16 rows x 512, stride 520): conflict-free (1040 % 128 = 16)
    uint32_t aAddr = Hb_u32 + (uint32_t)((lane & 15) * 1040 + ((lane & 16) ? 16 : 0));
    // ldsm B lane addresses: warp's 32-row block, gate-aligned (proven mapping)
    uint32_t bA0 = Bs_u32 + (uint32_t)(((warp * 32 + (lane & 7) + ((lane & 16) ? 8 : 0)) * 520) * 2
                                       + ((lane & 8) ? 16 : 0));
    uint32_t bA1 = bA0 + 16 * 1040;

    // remote h-buffer bases for all cluster CTAs
    uint32_t remo[CSZ];
#pragma unroll
    for (int d = 0; d < CSZ; d++) remo[d] = mapa_u32(Hb_u32, (uint32_t)d);

    // this lane's h-chunk byte offsets inside a buffer:
    //   rows gid, gid+8; units u = (4*rank + warp)*8 + tg*2  -> col byte u*2
    uint32_t co  = (uint32_t)(gid * 1040 + rank * 64 + warp * 16 + tg * 4);
    int rowG = r0 + gid;               // global batch row (also rowG+8)
    int cuW  = (int)rank * 4 + warp;   // this warp's u-group

    float c00 = 0.0f, c01 = 0.0f, c10 = 0.0f, c11 = 0.0f;

    for (int t = 0; t < TT; t++) {
        uint32_t bro = (uint32_t)((t & 1) * 16640);        // read buffer offset
        uint32_t bwo = bro ^ 16640u;                       // write buffer offset

        // z_x prefetch (global, independent of the barrier)
        const float* zxr0 = g_zx + ((size_t)t * BB + rowG) * ZZ + cuW * CPC + tg * 2;
        const float* zxr1 = zxr0 + 8 * ZZ;
        float2 zi0 = *(const float2*)(zxr0);
        float2 zf0 = *(const float2*)(zxr0 + 8);
        float2 zg0 = *(const float2*)(zxr0 + 16);
        float2 zo0 = *(const float2*)(zxr0 + 24);
        float2 zi1 = *(const float2*)(zxr1);
        float2 zf1 = *(const float2*)(zxr1 + 8);
        float2 zg1 = *(const float2*)(zxr1 + 16);
        float2 zo1 = *(const float2*)(zxr1 + 24);

        // wait for h(t) (paired with the arrive at the end of step t-1 / the init sync)
        if (t > 0) cluster_wait();

        float acc[4][4];   // [gate][q]
#pragma unroll
        for (int g = 0; g < 4; g++)
#pragma unroll
            for (int q = 0; q < 4; q++) acc[g][q] = 0.0f;

#pragma unroll
        for (int ks = 0; ks < 32; ks++) {
            uint32_t kb = (uint32_t)(ks * 32);
            uint32_t a0, a1, a2, a3, b0, b1, b2, b3, b4, b5, b6, b7;
            ldsm_x4(a0, a1, a2, a3, aAddr + bro + kb);
            ldsm_x4(b0, b1, b2, b3, bA0 + kb);
            ldsm_x4(b4, b5, b6, b7, bA1 + kb);
            mma_bf16(acc[0][0], acc[0][1], acc[0][2], acc[0][3], a0, a1, a2, a3, b0, b1);
            mma_bf16(acc[1][0], acc[1][1], acc[1][2], acc[1][3], a0, a1, a2, a3, b2, b3);
            mma_bf16(acc[2][0], acc[2][1], acc[2][2], acc[2][3], a0, a1, a2, a3, b4, b5);
            mma_bf16(acc[3][0], acc[3][1], acc[3][2], acc[3][3], a0, a1, a2, a3, b6, b7);
        }

        // gate update fully in registers
        uint32_t v0, v1;
        {
            float i0 = sigm_apx(zi0.x + acc[0][0]), fg0 = sigm_apx(zf0.x + acc[1][0]);
            float gg0 = tanh_apx(zg0.x + acc[2][0]), o0 = sigm_apx(zo0.x + acc[3][0]);
            c00 = fg0 * c00 + i0 * gg0;
            float h00 = o0 * tanh_apx(c00);

            float i1 = sigm_apx(zi0.y + acc[0][1]), fg1 = sigm_apx(zf0.y + acc[1][1]);
            float gg1 = tanh_apx(zg0.y + acc[2][1]), o1 = sigm_apx(zo0.y + acc[3][1]);
            c01 = fg1 * c01 + i1 * gg1;
            float h01 = o1 * tanh_apx(c01);

            float i2 = sigm_apx(zi1.x + acc[0][2]), fg2 = sigm_apx(zf1.x + acc[1][2]);
            float gg2 = tanh_apx(zg1.x + acc[2][2]), o2 = sigm_apx(zo1.x + acc[3][2]);
            c10 = fg2 * c10 + i2 * gg2;
            float h10 = o2 * tanh_apx(c10);

            float i3 = sigm_apx(zi1.y + acc[0][3]), fg3 = sigm_apx(zf1.y + acc[1][3]);
            float gg3 = tanh_apx(zg1.y + acc[2][3]), o3 = sigm_apx(zo1.y + acc[3][3]);
            c11 = fg3 * c11 + i3 * gg3;
            float h11 = o3 * tanh_apx(c11);

            __nv_bfloat162 hA, hB;
            hA.x = __float2bfloat16(h00); hA.y = __float2bfloat16(h01);
            hB.x = __float2bfloat16(h10); hB.y = __float2bfloat16(h11);
            v0 = *(uint32_t*)&hA;
            v1 = *(uint32_t*)&hB;
        }

        // broadcast this lane's 4 h-values to all cluster CTAs' write buffer
        {
            uint32_t off0 = bwo + co;
            uint32_t off1 = off0 + 8 * 1040;
#pragma unroll
            for (int d = 0; d < CSZ; d++) {
                st_cluster_u32(remo[d] + off0, v0);
                st_cluster_u32(remo[d] + off1, v1);
            }
        }

        // publish h(t+1): per-thread release-arrive (orders this thread's remote stores)
        cluster_arrive();
    }

    // final: buf0 holds h(512); dump this CTA's designated row to global for the head
    cluster_wait();
    {
        const bf16* srcrow = (const bf16*)((const char*)Hb + (size_t)rank * 1040);
        *(uint2*)(g_hbuf + (size_t)(r0 + (int)rank) * UU + tid * 4) =
            *(const uint2*)(srcrow + tid * 4);
    }
}

// ---------------- head: per-batch MLP ----------------
__global__ __launch_bounds__(128) void k_head(const float* __restrict__ W1, const float* __restrict__ b1,
                                              const float* __restrict__ W2, const float* __restrict__ b2,
                                              const float* __restrict__ W3, const float* __restrict__ b3,
                                              float* __restrict__ out) {
    __shared__ float hsm[UU];
    __shared__ float h1[128];
    __shared__ float red[64];
    int b   = blockIdx.x;
    int tid = threadIdx.x;

    for (int i = tid; i < UU; i += 128)
        hsm[i] = __bfloat162float(g_hbuf[(size_t)b * UU + i]);
    __syncthreads();

    float a1 = b1[tid];
#pragma unroll 8
    for (int k = 0; k < UU; k++) a1 += hsm[k] * W1[k * 128 + tid];
    h1[tid] = fmaxf(a1, 0.0f);
    __syncthreads();

    if (tid < 64) {
        float a2 = b2[tid];
#pragma unroll 8
        for (int k = 0; k < 128; k++) a2 += h1[k] * W2[k * 64 + tid];
        a2 = fmaxf(a2, 0.0f);
        red[tid] = a2 * W3[tid];
    }
    __syncthreads();

    if (tid == 0) {
        float s = b3[0];
#pragma unroll 8
        for (int k = 0; k < 64; k++) s += red[k];
        out[b] = 1.0f / (1.0f + expf(-s));
    }
}

// ---------------- launch ----------------
extern "C" void kernel_launch(void* const* d_in, const int* in_sizes, int n_in,
                              void* d_out, int out_size) {
    const int*   sentence = (const int*)  d_in[0];
    const float* emb      = (const float*)d_in[1];
    const float* Wx       = (const float*)d_in[2];
    const float* Wh       = (const float*)d_in[3];
    const float* bvec     = (const float*)d_in[4];
    const float* W1       = (const float*)d_in[5];
    const float* b1       = (const float*)d_in[6];
    const float* W2       = (const float*)d_in[7];
    const float* b2       = (const float*)d_in[8];
    const float* W3       = (const float*)d_in[9];
    const float* b3       = (const float*)d_in[10];
    float* out = (float*)d_out;

    static bool attr_done = false;
    if (!attr_done) {
        cudaFuncSetAttribute(k_phase1, cudaFuncAttributeMaxDynamicSharedMemorySize, 52736);
        cudaFuncSetAttribute(k_recur,  cudaFuncAttributeNonPortableClusterSizeAllowed, 1);
        cudaFuncSetAttribute(k_recur,  cudaFuncAttributeMaxDynamicSharedMemorySize, 166464);
        attr_done = true;
    }

    k_cvt_emb<<<4096, 256>>>(emb);
    k_gather_wx<<<2048, 256>>>(Wx, bvec);
    k_gather_wh<<<4096, 256>>>(Wh);

    k_phase1<<<1024, 256, 52736>>>(sentence);

    k_recur<<<128, 128, 166464>>>();

    k_head<<<128, 128>>>(W1, b1, W2, b2, W3, b3, out);
}

// round 12
// speedup vs baseline: 2.2822x; 1.5554x over previous
#include <cuda_runtime.h>
#include <cuda_bf16.h>
#include <cstdint>
#include <cstddef>

// Problem dims
#define BB   128
#define TT   512
#define EE   256
#define UU   512
#define ZZ   2048          // 4*U
#define NCU  64            // u-groups (8 units each)
#define UT   8             // units per CTA group
#define CPC  32            // z-cols per CTA (4 gates * 8 units)
#define NCTA 128           // persistent grid

typedef __nv_bfloat16 bf16;

// ---------------- scratch (device globals; no allocations) ----------------
__device__ __align__(16) bf16  g_emb16[32000 * EE];          // bf16 embedding (16.4 MB)
__device__ __align__(16) bf16  g_WxGt [NCU * CPC * EE];      // gathered Wx, [cu][jp][k] (1 MB)
__device__ __align__(16) bf16  g_WhGt [NCU * CPC * UU];      // gathered Wh, [cu][jp][k] (2 MB)
__device__ __align__(16) float g_bG   [ZZ];                  // gathered bias
__device__ __align__(1024) bf16 g_hbuf[2 * BB * UU];         // h double buffer
__device__ __align__(16) unsigned g_flags[NCTA * 32];        // per-CTA epoch flags, 128B padded

// gather map: gc -> original column
__device__ __forceinline__ int orig_col(int gc) {
    int cu   = gc >> 5;
    int gate = (gc >> 3) & 3;
    int j    = gc & 7;
    return gate * UU + cu * UT + j;
}

__device__ __forceinline__ float tanh_apx(float x) {
    float y;
    asm("tanh.approx.f32 %0, %1;" : "=f"(y) : "f"(x));
    return y;
}
__device__ __forceinline__ float sigm_apx(float x) {
    return fmaf(tanh_apx(0.5f * x), 0.5f, 0.5f);
}

__device__ __forceinline__ void mma_bf16(float& d0, float& d1, float& d2, float& d3,
                                         uint32_t a0, uint32_t a1, uint32_t a2, uint32_t a3,
                                         uint32_t b0, uint32_t b1) {
    asm volatile(
        "mma.sync.aligned.m16n8k16.row.col.f32.bf16.bf16.f32 "
        "{%0,%1,%2,%3}, {%4,%5,%6,%7}, {%8,%9}, {%0,%1,%2,%3};"
        : "+f"(d0), "+f"(d1), "+f"(d2), "+f"(d3)
        : "r"(a0), "r"(a1), "r"(a2), "r"(a3), "r"(b0), "r"(b1));
}

__device__ __forceinline__ void ldsm_x4(uint32_t& r0, uint32_t& r1, uint32_t& r2, uint32_t& r3,
                                        uint32_t addr) {
    asm volatile("ldmatrix.sync.aligned.m8n8.x4.shared.b16 {%0,%1,%2,%3}, [%4];"
                 : "=r"(r0), "=r"(r1), "=r"(r2), "=r"(r3) : "r"(addr));
}

__device__ __forceinline__ void cp_async16(uint32_t dst_smem, const void* src) {
    asm volatile("cp.async.cg.shared.global [%0], [%1], 16;" :: "r"(dst_smem), "l"(src));
}

// ---------------- init kernels ----------------
__global__ void k_cvt_emb(const float* __restrict__ src) {
    int n4 = 32000 * EE / 4;
    for (int i = blockIdx.x * blockDim.x + threadIdx.x; i < n4; i += gridDim.x * blockDim.x) {
        float4 v = *(const float4*)(src + (size_t)i * 4);
        bf16* d = g_emb16 + (size_t)i * 4;
        d[0] = __float2bfloat16(v.x);
        d[1] = __float2bfloat16(v.y);
        d[2] = __float2bfloat16(v.z);
        d[3] = __float2bfloat16(v.w);
    }
}

// gather Wx into [cu][jp][k] (32 rows x 256 K per u-group), like Wh
__global__ void k_gather_wx(const float* __restrict__ Wx, const float* __restrict__ bvec) {
    int n = NCU * CPC * EE;
    for (int i = blockIdx.x * blockDim.x + threadIdx.x; i < n; i += gridDim.x * blockDim.x) {
        int cu = i >> 13;             // / (32*256)
        int jp = (i >> 8) & 31;
        int k  = i & 255;
        int gate = jp >> 3;
        int j    = jp & 7;
        g_WxGt[i] = __float2bfloat16(Wx[(size_t)k * ZZ + gate * UU + cu * UT + j]);
    }
    int t = blockIdx.x * blockDim.x + threadIdx.x;
    if (t < ZZ) g_bG[t] = bvec[orig_col(t)];
}

__global__ void k_gather_wh(const float* __restrict__ Wh) {
    int n = NCU * CPC * UU;
    for (int i = blockIdx.x * blockDim.x + threadIdx.x; i < n; i += gridDim.x * blockDim.x) {
        int cu = i >> 14;             // / (32*512)
        int jp = (i >> 9) & 31;
        int k  = i & 511;
        int gate = jp >> 3;
        int j    = jp & 7;
        g_WhGt[i] = __float2bfloat16(Wh[(size_t)k * ZZ + gate * UU + cu * UT + j]);
    }
}

__global__ void k_zero_state() {
    int tid = blockIdx.x * blockDim.x + threadIdx.x;
    int n = BB * UU;
    for (int i = tid; i < n; i += gridDim.x * blockDim.x)
        g_hbuf[i] = __float2bfloat16(0.0f);     // buffer 0 (read by step 0)
    for (int i = tid; i < NCTA * 32; i += gridDim.x * blockDim.x)
        g_flags[i] = 0u;
}

// ---------------- fused persistent recurrence ----------------
// 128 CTAs x 128 threads (4 warps). cu = bx&63, mg = bx>>6; warp w = rows [m0+16w,+16).
// Per step: x-GEMM (K=256, from prefetched emb tile + resident Wx) BEFORE the flag wait,
// then the proven h pipeline (poll >= t, 4-chunk cp.async staging, 32 h-GEMM iters),
// register gate math, release-publish t+1. Bias pre-loaded into accumulators.
// dyn smem layout (bytes):
//   Bs  (Wh 32x520)        @ 0       33280
//   hs  (h tile 64x520)    @ 33280   66560
//   Wxs (Wx 32x264)        @ 99840   16896
//   Es  (emb 2 x 64x264)   @ 116736  67584
//   tks (int 2x64)         @ 184320  512     -> total 184832
__global__ __launch_bounds__(128) void k_recur(const int* __restrict__ sentence) {
    extern __shared__ __align__(128) char dsm[];
    bf16* Bs  = (bf16*)dsm;
    int*  tks = (int*)(dsm + 184320);

    uint32_t base_u32 = (uint32_t)__cvta_generic_to_shared(dsm);
    uint32_t Bs_u32   = base_u32;
    uint32_t hs_u32   = base_u32 + 33280;
    uint32_t Wxs_u32  = base_u32 + 99840;
    uint32_t Es_u32   = base_u32 + 116736;

    bf16* Wxs = (bf16*)(dsm + 99840);

    int tid  = threadIdx.x;
    int warp = tid >> 5;
    int lane = tid & 31;
    int tg   = lane & 3;
    int gid  = lane >> 2;

    int cu = blockIdx.x & 63;
    int mg = blockIdx.x >> 6;
    int m0 = mg * 64;
    int wm = warp * 16;

    // preload Wh slice (32 x 512 bf16, stride 520): 2048 uint4 = 32 rows x 64 uint4
    {
        const bf16* Wp = g_WhGt + (size_t)cu * CPC * UU;
        for (int i = tid; i < 2048; i += 128) {
            int n   = i >> 6;
            int seg = i & 63;
            *(uint4*)(Bs + n * 520 + seg * 8) = *(const uint4*)(Wp + n * UU + seg * 8);
        }
    }
    // preload Wx slice (32 x 256 bf16, stride 264): 1024 uint4 = 32 rows x 32 uint4  [BUGFIX]
    {
        const bf16* Wp = g_WxGt + (size_t)cu * CPC * EE;
        for (int i = tid; i < 1024; i += 128) {
            int row = i >> 5;
            int seg = i & 31;
            *(uint4*)(Wxs + row * 264 + seg * 8) = *(const uint4*)(Wp + row * EE + seg * 8);
        }
    }

    // per-lane bias (acc init values)
    float bi[4][2];
#pragma unroll
    for (int g = 0; g < 4; g++) {
        bi[g][0] = g_bG[cu * 32 + g * 8 + tg * 2];
        bi[g][1] = g_bG[cu * 32 + g * 8 + tg * 2 + 1];
    }

    // ldsm lane addresses (byte offsets)
    uint32_t aAddrH = hs_u32 + (uint32_t)((wm + (lane & 15)) * 1040 + ((lane & 16) ? 16 : 0));
    uint32_t bH0 = Bs_u32 + (uint32_t)(((0  + (lane & 7) + ((lane & 16) ? 8 : 0)) * 520) * 2 + ((lane & 8) ? 16 : 0));
    uint32_t bH1 = Bs_u32 + (uint32_t)(((16 + (lane & 7) + ((lane & 16) ? 8 : 0)) * 520) * 2 + ((lane & 8) ? 16 : 0));
    uint32_t aAddrXbase = Es_u32 + (uint32_t)((wm + (lane & 15)) * 528 + ((lane & 16) ? 16 : 0));
    uint32_t bX0 = Wxs_u32 + (uint32_t)(((0  + (lane & 7) + ((lane & 16) ? 8 : 0)) * 264) * 2 + ((lane & 8) ? 16 : 0));
    uint32_t bX1 = Wxs_u32 + (uint32_t)(((16 + (lane & 7) + ((lane & 16) ? 8 : 0)) * 264) * 2 + ((lane & 8) ? 16 : 0));

    // gate ownership: rows (m0+wm+gid, +8), units (cu*8 + tg*2, +1)
    int rowA = m0 + wm + gid;
    float c00 = 0.0f, c01 = 0.0f, c10 = 0.0f, c11 = 0.0f;

    unsigned* myflag   = g_flags + (size_t)(mg * 64 + cu) * 32;
    unsigned* pollflag = g_flags + (size_t)(mg * 64 + (tid & 63)) * 32;

    // emb prefetch lane roles: 2 threads per row, 256B per thread
    int erow  = tid >> 1;
    int ehalf = tid & 1;

    // ---- prologue: tokens + emb tile for t = 0 ----
    if (tid < 64) tks[tid] = sentence[(m0 + tid) * TT];
    __syncthreads();
    {
        int tok = tks[erow];
        const bf16* esrc = g_emb16 + (size_t)tok * EE + ehalf * 128;
        uint32_t edst = Es_u32 + (uint32_t)(erow * 528 + ehalf * 256);
#pragma unroll
        for (int s = 0; s < 16; s++) cp_async16(edst + s * 16, esrc + s * 8);
    }
    asm volatile("cp.async.commit_group;" ::: "memory");

    for (int t = 0; t < TT; t++) {
        const bf16* hsrc = g_hbuf + (size_t)(t & 1) * (BB * UU);
        bf16*       hdst = g_hbuf + (size_t)((t + 1) & 1) * (BB * UU);

        // (a) drain all prior async copies (emb(t) + last step's h chunks), make visible
        asm volatile("cp.async.wait_group 0;" ::: "memory");
        __syncthreads();

        // (b) tokens for t+1 into the other buffer
        if (t < TT - 1 && tid < 64)
            tks[((t + 1) & 1) * 64 + tid] = sentence[(m0 + tid) * TT + t + 1];

        // (c) x-GEMM: acc = bias + x(t) @ Wx  (16 K-iters, K=256)
        float acc[4][4];
#pragma unroll
        for (int g = 0; g < 4; g++) {
            acc[g][0] = bi[g][0]; acc[g][1] = bi[g][1];
            acc[g][2] = bi[g][0]; acc[g][3] = bi[g][1];
        }
        {
            uint32_t aX = aAddrXbase + (uint32_t)((t & 1) * 33792);
#pragma unroll
            for (int kx = 0; kx < 16; kx++) {
                uint32_t kb = (uint32_t)(kx * 32);
                uint32_t a0, a1, a2, a3, b0, b1, b2, b3, b4, b5, b6, b7;
                ldsm_x4(a0, a1, a2, a3, aX + kb);
                ldsm_x4(b0, b1, b2, b3, bX0 + kb);
                ldsm_x4(b4, b5, b6, b7, bX1 + kb);
                mma_bf16(acc[0][0], acc[0][1], acc[0][2], acc[0][3], a0, a1, a2, a3, b0, b1);
                mma_bf16(acc[1][0], acc[1][1], acc[1][2], acc[1][3], a0, a1, a2, a3, b2, b3);
                mma_bf16(acc[2][0], acc[2][1], acc[2][2], acc[2][3], a0, a1, a2, a3, b4, b5);
                mma_bf16(acc[3][0], acc[3][1], acc[3][2], acc[3][3], a0, a1, a2, a3, b6, b7);
            }
        }

        // (d) wait for h(t): all producer flags >= t
        if (tid < 64) {
            unsigned v;
            do {
                asm volatile("ld.acquire.gpu.u32 %0, [%1];" : "=r"(v) : "l"(pollflag));
            } while (v < (unsigned)t);
        }
        __syncthreads();   // flags passed + tks visible + Es[(t+1)&1] free

        // (e) issue h staging (4 chunks of 128 cols) then emb(t+1) — 5 FIFO groups
#pragma unroll
        for (int c = 0; c < 4; c++) {
#pragma unroll
            for (int r = 0; r < 8; r++) {
                int i   = r * 128 + tid;
                int row = i >> 4;
                int seg = i & 15;
                cp_async16(hs_u32 + (uint32_t)((row * 520 + c * 128 + seg * 8) * 2),
                           hsrc + (size_t)(m0 + row) * UU + c * 128 + seg * 8);
            }
            asm volatile("cp.async.commit_group;" ::: "memory");
        }
        if (t < TT - 1) {
            int p1  = (t + 1) & 1;
            int tok = tks[p1 * 64 + erow];
            const bf16* esrc = g_emb16 + (size_t)tok * EE + ehalf * 128;
            uint32_t edst = Es_u32 + (uint32_t)(p1 * 33792 + erow * 528 + ehalf * 256);
#pragma unroll
            for (int s = 0; s < 16; s++) cp_async16(edst + s * 16, esrc + s * 8);
        }
        asm volatile("cp.async.commit_group;" ::: "memory");   // group 5 (maybe empty)

        // (f) h-GEMM: 4 chunks, pipelined waits 4/3/2/1
#define COMPUTE_CHUNK(CC, WG)                                                       \
        asm volatile("cp.async.wait_group " #WG ";" ::: "memory");                  \
        __syncthreads();                                                            \
        _Pragma("unroll")                                                           \
        for (int ks = CC * 8; ks < CC * 8 + 8; ks++) {                              \
            uint32_t kb = (uint32_t)(ks * 32);                                      \
            uint32_t a0, a1, a2, a3, b0, b1, b2, b3, b4, b5, b6, b7;                \
            ldsm_x4(a0, a1, a2, a3, aAddrH + kb);                                   \
            ldsm_x4(b0, b1, b2, b3, bH0 + kb);                                      \
            ldsm_x4(b4, b5, b6, b7, bH1 + kb);                                      \
            mma_bf16(acc[0][0], acc[0][1], acc[0][2], acc[0][3], a0, a1, a2, a3, b0, b1); \
            mma_bf16(acc[1][0], acc[1][1], acc[1][2], acc[1][3], a0, a1, a2, a3, b2, b3); \
            mma_bf16(acc[2][0], acc[2][1], acc[2][2], acc[2][3], a0, a1, a2, a3, b4, b5); \
            mma_bf16(acc[3][0], acc[3][1], acc[3][2], acc[3][3], a0, a1, a2, a3, b6, b7); \
        }

        COMPUTE_CHUNK(0, 4)
        COMPUTE_CHUNK(1, 3)
        COMPUTE_CHUNK(2, 2)
        COMPUTE_CHUNK(3, 1)
#undef COMPUTE_CHUNK

        // (g) gate update fully in registers
        {
            float i0 = sigm_apx(acc[0][0]), fg0 = sigm_apx(acc[1][0]);
            float gg0 = tanh_apx(acc[2][0]), o0 = sigm_apx(acc[3][0]);
            c00 = fg0 * c00 + i0 * gg0;
            float h00 = o0 * tanh_apx(c00);

            float i1 = sigm_apx(acc[0][1]), fg1 = sigm_apx(acc[1][1]);
            float gg1 = tanh_apx(acc[2][1]), o1 = sigm_apx(acc[3][1]);
            c01 = fg1 * c01 + i1 * gg1;
            float h01 = o1 * tanh_apx(c01);

            float i2 = sigm_apx(acc[0][2]), fg2 = sigm_apx(acc[1][2]);
            float gg2 = tanh_apx(acc[2][2]), o2 = sigm_apx(acc[3][2]);
            c10 = fg2 * c10 + i2 * gg2;
            float h10 = o2 * tanh_apx(c10);

            float i3 = sigm_apx(acc[0][3]), fg3 = sigm_apx(acc[1][3]);
            float gg3 = tanh_apx(acc[2][3]), o3 = sigm_apx(acc[3][3]);
            c11 = fg3 * c11 + i3 * gg3;
            float h11 = o3 * tanh_apx(c11);

            __nv_bfloat162 hA, hB;
            hA.x = __float2bfloat16(h00); hA.y = __float2bfloat16(h01);
            hB.x = __float2bfloat16(h10); hB.y = __float2bfloat16(h11);
            size_t base = (size_t)rowA * UU + cu * UT + tg * 2;
            *(__nv_bfloat162*)(hdst + base)          = hA;
            *(__nv_bfloat162*)(hdst + base + 8 * UU) = hB;
        }

        // (h) publish: h(t+1) written and h(t) fully consumed
        __syncthreads();
        if (tid == 0) {
            asm volatile("st.release.gpu.u32 [%0], %1;" :: "l"(myflag), "r"(t + 1) : "memory");
        }
    }
}

// ---------------- head: per-batch MLP (h(512) in buffer 0, plain layout) ----------------
__global__ __launch_bounds__(128) void k_head(const float* __restrict__ W1, const float* __restrict__ b1,
                                              const float* __restrict__ W2, const float* __restrict__ b2,
                                              const float* __restrict__ W3, const float* __restrict__ b3,
                                              float* __restrict__ out) {
    __shared__ float hsm[UU];
    __shared__ float h1[128];
    __shared__ float red[64];
    int b   = blockIdx.x;
    int tid = threadIdx.x;

    for (int i = tid; i < UU; i += 128)
        hsm[i] = __bfloat162float(g_hbuf[(size_t)b * UU + i]);
    __syncthreads();

    float a1 = b1[tid];
#pragma unroll 8
    for (int k = 0; k < UU; k++) a1 += hsm[k] * W1[k * 128 + tid];
    h1[tid] = fmaxf(a1, 0.0f);
    __syncthreads();

    if (tid < 64) {
        float a2 = b2[tid];
#pragma unroll 8
        for (int k = 0; k < 128; k++) a2 += h1[k] * W2[k * 64 + tid];
        a2 = fmaxf(a2, 0.0f);
        red[tid] = a2 * W3[tid];
    }
    __syncthreads();

    if (tid == 0) {
        float s = b3[0];
#pragma unroll 8
        for (int k = 0; k < 64; k++) s += red[k];
        out[b] = 1.0f / (1.0f + expf(-s));
    }
}

// ---------------- launch ----------------
extern "C" void kernel_launch(void* const* d_in, const int* in_sizes, int n_in,
                              void* d_out, int out_size) {
    const int*   sentence = (const int*)  d_in[0];
    const float* emb      = (const float*)d_in[1];
    const float* Wx       = (const float*)d_in[2];
    const float* Wh       = (const float*)d_in[3];
    const float* bvec     = (const float*)d_in[4];
    const float* W1       = (const float*)d_in[5];
    const float* b1       = (const float*)d_in[6];
    const float* W2       = (const float*)d_in[7];
    const float* b2       = (const float*)d_in[8];
    const float* W3       = (const float*)d_in[9];
    const float* b3       = (const float*)d_in[10];
    float* out = (float*)d_out;

    static bool attr_done = false;
    if (!attr_done) {
        cudaFuncSetAttribute(k_recur, cudaFuncAttributeMaxDynamicSharedMemorySize, 184832);
        attr_done = true;
    }

    k_cvt_emb<<<4096, 256>>>(emb);
    k_gather_wx<<<2048, 256>>>(Wx, bvec);
    k_gather_wh<<<4096, 256>>>(Wh);
    k_zero_state<<<256, 256>>>();

    k_recur<<<NCTA, 128, 184832>>>(sentence);

    k_head<<<128, 128>>>(W1, b1, W2, b2, W3, b3, out);
}